// round 12
// baseline (speedup 1.0000x reference)
#include <cuda_runtime.h>
#include <cuda_fp16.h>
#include <cstdint>

#define N_NODES 100000
#define E_EDGES 1600000
#define IN_CH   128
#define HEADS   4
#define OUT_CH  32
#define OC      (HEADS * OUT_CH)   // 128
#define NEG_SLOPE 0.2f

#define SCAN_BLK 1024
#define N_SCAN_BLOCKS ((N_NODES + SCAN_BLK - 1) / SCAN_BLK)   // 98
#define GEMM_CTAS ((N_NODES + 127) / 128)                     // 782

// ---------------- scratch (device globals; no allocation allowed) ----------
__device__ __align__(16) __half g_hh[(size_t)GEMM_CTAS * 128 * OC]; // fp16 h (padded)
__device__ __align__(16) float  g_ssrc[N_NODES * HEADS];
__device__ __align__(16) float  g_sdst[N_NODES * HEADS];
__device__ int g_csr_src[E_EDGES];
__device__ int g_rank[E_EDGES];
__device__ int g_deg[N_NODES];
__device__ int g_off[N_NODES];            // local (per-block) exclusive prefix
__device__ int g_bsum[N_SCAN_BLOCKS];
__device__ int g_bpre[N_SCAN_BLOCKS];
__device__ unsigned g_maxss[HEADS];
__device__ int g_is64;

__device__ __forceinline__ unsigned fenc(float f) {
    unsigned u = __float_as_uint(f);
    return (u & 0x80000000u) ? ~u : (u | 0x80000000u);
}
__device__ __forceinline__ float fdec(unsigned u) {
    return (u & 0x80000000u) ? __uint_as_float(u ^ 0x80000000u)
                             : __uint_as_float(~u);
}
__device__ __forceinline__ float leaky(float v) {
    return (v >= 0.f) ? v : NEG_SLOPE * v;
}
// global offset of node i (local scan + block prefix)
__device__ __forceinline__ int off_of(int i) {
    return __ldg(g_off + i) + __ldg(g_bpre + (i >> 10));
}

__device__ __forceinline__ void mma16816(float& d0, float& d1, float& d2, float& d3,
                                         unsigned a0, unsigned a1, unsigned a2, unsigned a3,
                                         unsigned b0, unsigned b1) {
    asm volatile("mma.sync.aligned.m16n8k16.row.col.f32.f16.f16.f32 "
                 "{%0,%1,%2,%3}, {%4,%5,%6,%7}, {%8,%9}, {%0,%1,%2,%3};"
                 : "+f"(d0), "+f"(d1), "+f"(d2), "+f"(d3)
                 : "r"(a0), "r"(a1), "r"(a2), "r"(a3), "r"(b0), "r"(b1));
}

// ---------------- K0: init + parallel dtype detect ---------------------------
__global__ void k_init(const unsigned* __restrict__ ei32) {
    const int i = blockIdx.x * blockDim.x + threadIdx.x;
    if (i < N_NODES) g_deg[i] = 0;
    if (i < HEADS) g_maxss[i] = fenc(-__int_as_float(0x7f800000));
    if (blockIdx.x == 0 && threadIdx.x < 64) {
        const unsigned w = ei32[2 * threadIdx.x + 1];
        const unsigned nz = __ballot_sync(0xffffffffu, w != 0u);
        __shared__ int anynz;
        if (threadIdx.x == 0) anynz = 0;
        __syncthreads();
        if (nz) atomicOr(&anynz, 1);
        __syncthreads();
        if (threadIdx.x == 0) g_is64 = anynz ? 0 : 1;
    }
}

// ---------------- K1: tensor-core GEMM + fused scores -----------------------
#define APAD 72   // 64 + 8 halves pad
__global__ void __launch_bounds__(256) k_gemm_mma(const float* __restrict__ x,
                                                  const float* __restrict__ W,
                                                  const float* __restrict__ att) {
    __shared__ __half As[128][APAD];
    __shared__ __half Bs[128][APAD];

    const int nbase = blockIdx.x * 128;
    const int t = threadIdx.x;
    const int wid = t >> 5;
    const int lane = t & 31;
    const int g = lane >> 2;
    const int tid = lane & 3;

    float d[16][4];
    #pragma unroll
    for (int nt = 0; nt < 16; nt++)
        #pragma unroll
        for (int q = 0; q < 4; q++) d[nt][q] = 0.f;

    #pragma unroll
    for (int kp = 0; kp < 2; kp++) {
        #pragma unroll
        for (int i = 0; i < 8; i++) {
            const int id = t + i * 256;
            const int row = id >> 4;
            const int c4 = (id & 15) * 4;
            const int node = nbase + row;
            float4 v = make_float4(0.f, 0.f, 0.f, 0.f);
            if (node < N_NODES)
                v = __ldg((const float4*)(x + (size_t)node * IN_CH + kp * 64 + c4));
            __half h4[4] = {__float2half_rn(v.x), __float2half_rn(v.y),
                            __float2half_rn(v.z), __float2half_rn(v.w)};
            *(uint2*)&As[row][c4] = *(uint2*)h4;
        }
        #pragma unroll
        for (int i = 0; i < 8; i++) {
            const int id = t + i * 256;
            const int k = id >> 5;
            const int n4 = (id & 31) * 4;
            const float4 w4 = __ldg((const float4*)(W + (size_t)(kp * 64 + k) * OC + n4));
            Bs[n4 + 0][k] = __float2half_rn(w4.x);
            Bs[n4 + 1][k] = __float2half_rn(w4.y);
            Bs[n4 + 2][k] = __float2half_rn(w4.z);
            Bs[n4 + 3][k] = __float2half_rn(w4.w);
        }
        __syncthreads();

        const int r0 = wid * 16 + g;
        #pragma unroll
        for (int ks = 0; ks < 4; ks++) {
            const int kk = ks * 16 + tid * 2;
            const unsigned a0 = *(const unsigned*)&As[r0][kk];
            const unsigned a1 = *(const unsigned*)&As[r0 + 8][kk];
            const unsigned a2 = *(const unsigned*)&As[r0][kk + 8];
            const unsigned a3 = *(const unsigned*)&As[r0 + 8][kk + 8];
            #pragma unroll
            for (int nt = 0; nt < 16; nt++) {
                const int n = nt * 8 + g;
                const unsigned b0 = *(const unsigned*)&Bs[n][kk];
                const unsigned b1 = *(const unsigned*)&Bs[n][kk + 8];
                mma16816(d[nt][0], d[nt][1], d[nt][2], d[nt][3],
                         a0, a1, a2, a3, b0, b1);
            }
        }
        __syncthreads();
    }

    // ---- epilogue: store h (fp16) + fused scores ----
    const int node0 = nbase + wid * 16 + g;
    const int node1 = node0 + 8;

    #pragma unroll
    for (int nt = 0; nt < 16; nt++) {
        const int col = nt * 8 + tid * 2;
        const __half2 h01 = __floats2half2_rn(d[nt][0], d[nt][1]);
        const __half2 h23 = __floats2half2_rn(d[nt][2], d[nt][3]);
        *(__half2*)(g_hh + (size_t)node0 * OC + col) = h01;
        *(__half2*)(g_hh + (size_t)node1 * OC + col) = h23;
    }

    float ssA[4] = {0,0,0,0}, sdA[4] = {0,0,0,0};
    float ssB[4] = {0,0,0,0}, sdB[4] = {0,0,0,0};
    #pragma unroll
    for (int h = 0; h < 4; h++) {
        #pragma unroll
        for (int j = 0; j < 4; j++) {
            const int nt = h * 4 + j;
            const int off = j * 8 + tid * 2;
            const float2 as2 = __ldg((const float2*)(att + h * 64 + off));
            const float2 ad2 = __ldg((const float2*)(att + h * 64 + 32 + off));
            ssA[h] += d[nt][0] * as2.x + d[nt][1] * as2.y;
            sdA[h] += d[nt][0] * ad2.x + d[nt][1] * ad2.y;
            ssB[h] += d[nt][2] * as2.x + d[nt][3] * as2.y;
            sdB[h] += d[nt][2] * ad2.x + d[nt][3] * ad2.y;
        }
    }
    #pragma unroll
    for (int h = 0; h < 4; h++) {
        #pragma unroll
        for (int off = 1; off <= 2; off <<= 1) {
            ssA[h] += __shfl_xor_sync(0xffffffffu, ssA[h], off);
            sdA[h] += __shfl_xor_sync(0xffffffffu, sdA[h], off);
            ssB[h] += __shfl_xor_sync(0xffffffffu, ssB[h], off);
            sdB[h] += __shfl_xor_sync(0xffffffffu, sdB[h], off);
        }
    }
    if (tid == 0) {
        if (node0 < N_NODES) {
            *(float4*)(g_ssrc + (size_t)node0 * 4) = make_float4(ssA[0], ssA[1], ssA[2], ssA[3]);
            *(float4*)(g_sdst + (size_t)node0 * 4) = make_float4(sdA[0], sdA[1], sdA[2], sdA[3]);
        }
        if (node1 < N_NODES) {
            *(float4*)(g_ssrc + (size_t)node1 * 4) = make_float4(ssB[0], ssB[1], ssB[2], ssB[3]);
            *(float4*)(g_sdst + (size_t)node1 * 4) = make_float4(sdB[0], sdB[1], sdB[2], sdB[3]);
        }
    }
    const float NINF = -__int_as_float(0x7f800000);
    float mm[4];
    #pragma unroll
    for (int h = 0; h < 4; h++) {
        float a = (node0 < N_NODES) ? ssA[h] : NINF;
        float b = (node1 < N_NODES) ? ssB[h] : NINF;
        mm[h] = fmaxf(a, b);
        #pragma unroll
        for (int off = 4; off <= 16; off <<= 1)
            mm[h] = fmaxf(mm[h], __shfl_xor_sync(0xffffffffu, mm[h], off));
    }
    if (lane < 4)
        atomicMax(&g_maxss[lane], fenc(mm[lane]));
}

// ---------------- K2: degree histogram + rank, 2 edges/thread ---------------
__global__ void k_hist(const void* __restrict__ ei) {
    const int e = (blockIdx.x * blockDim.x + threadIdx.x) * 2;
    if (e >= E_EDGES) return;
    int d0, d1;
    if (g_is64) {
        const uint4 dv = *(const uint4*)((const long long*)ei + E_EDGES + e);
        d0 = (int)dv.x; d1 = (int)dv.z;
    } else {
        const int2 dv = *(const int2*)((const int*)ei + E_EDGES + e);
        d0 = dv.x; d1 = dv.y;
    }
    const int r0 = atomicAdd(&g_deg[d0], 1);
    const int r1 = atomicAdd(&g_deg[d1], 1);
    *(int2*)(g_rank + e) = make_int2(r0, r1);
}

// ---------------- K3a/b: device-wide exclusive scan (no final pass) --------
__global__ void __launch_bounds__(SCAN_BLK) k_scan_local() {
    __shared__ int ws[32];
    const int t = threadIdx.x;
    const int lane = t & 31;
    const int warp = t >> 5;
    const int i = blockIdx.x * SCAN_BLK + t;

    const int val = (i < N_NODES) ? g_deg[i] : 0;
    int v = val;
    #pragma unroll
    for (int d = 1; d < 32; d <<= 1) {
        const int u = __shfl_up_sync(0xffffffffu, v, d);
        if (lane >= d) v += u;
    }
    if (lane == 31) ws[warp] = v;
    __syncthreads();
    if (warp == 0) {
        int w = ws[lane];
        #pragma unroll
        for (int d = 1; d < 32; d <<= 1) {
            const int u = __shfl_up_sync(0xffffffffu, w, d);
            if (lane >= d) w += u;
        }
        ws[lane] = w;
    }
    __syncthreads();
    const int incl = v + (warp ? ws[warp - 1] : 0);
    if (i < N_NODES) g_off[i] = incl - val;
    if (t == SCAN_BLK - 1) g_bsum[blockIdx.x] = incl;
}

__global__ void __launch_bounds__(128) k_scan_bsum() {
    __shared__ int ws[4];
    const int t = threadIdx.x;
    const int lane = t & 31;
    const int warp = t >> 5;
    const int val = (t < N_SCAN_BLOCKS) ? g_bsum[t] : 0;
    int v = val;
    #pragma unroll
    for (int d = 1; d < 32; d <<= 1) {
        const int u = __shfl_up_sync(0xffffffffu, v, d);
        if (lane >= d) v += u;
    }
    if (lane == 31) ws[warp] = v;
    __syncthreads();
    int wpre = 0;
    #pragma unroll
    for (int w = 0; w < 4; w++) if (w < warp) wpre += ws[w];
    if (t < N_SCAN_BLOCKS) g_bpre[t] = v - val + wpre;
}

// ---------------- K4: CSR scatter, 2 edges/thread, no atomics ---------------
__global__ void k_edge2(const void* __restrict__ ei) {
    const int e = (blockIdx.x * blockDim.x + threadIdx.x) * 2;
    if (e >= E_EDGES) return;
    int s0, s1, d0, d1;
    if (g_is64) {
        const uint4 sv = *(const uint4*)((const long long*)ei + e);
        const uint4 dv = *(const uint4*)((const long long*)ei + E_EDGES + e);
        s0 = (int)sv.x; s1 = (int)sv.z;
        d0 = (int)dv.x; d1 = (int)dv.z;
    } else {
        const int2 sv = *(const int2*)((const int*)ei + e);
        const int2 dv = *(const int2*)((const int*)ei + E_EDGES + e);
        s0 = sv.x; s1 = sv.y;
        d0 = dv.x; d1 = dv.y;
    }
    const int2 rk = *(const int2*)(g_rank + e);
    g_csr_src[off_of(d0) + rk.x] = s0;
    g_csr_src[off_of(d1) + rk.y] = s1;
}

// ---------------- K5: aggregation w/ on-the-fly softmax (1 warp/node) ------
__device__ __forceinline__ void edge_fma(int src, float sd, float bnd, int head, int c0,
                                         float4& acc, float& sumw) {
    const float ss = __ldg(g_ssrc + (size_t)src * 4 + head);
    const float w = __expf(leaky(ss + sd) - bnd);
    const uint2 r = *(const uint2*)(g_hh + (size_t)src * OC + c0);
    const float2 a = __half22float2(*(const __half2*)&r.x);
    const float2 b = __half22float2(*(const __half2*)&r.y);
    acc.x = fmaf(w, a.x, acc.x); acc.y = fmaf(w, a.y, acc.y);
    acc.z = fmaf(w, b.x, acc.z); acc.w = fmaf(w, b.y, acc.w);
    sumw += w;
}

__global__ void __launch_bounds__(256) k_aggregate(float* __restrict__ out,
                                                   const float* __restrict__ bias) {
    const int n = (blockIdx.x * blockDim.x + threadIdx.x) >> 5;
    if (n >= N_NODES) return;
    const int lane = threadIdx.x & 31;
    const int head = lane >> 3;
    const int c0 = lane * 4;

    const int beg = off_of(n);
    const int end = (n + 1 < N_NODES) ? off_of(n + 1) : E_EDGES;

    const float sd = __ldg(g_sdst + (size_t)n * 4 + head);
    const float bnd = leaky(fdec(g_maxss[head]) + sd);

    float4 acc = make_float4(0.f, 0.f, 0.f, 0.f);
    float sumw = 0.f;

    int p = beg;
    for (; p + 4 <= end; p += 4) {
        const int s0 = __ldg(g_csr_src + p);
        const int s1 = __ldg(g_csr_src + p + 1);
        const int s2 = __ldg(g_csr_src + p + 2);
        const int s3 = __ldg(g_csr_src + p + 3);
        edge_fma(s0, sd, bnd, head, c0, acc, sumw);
        edge_fma(s1, sd, bnd, head, c0, acc, sumw);
        edge_fma(s2, sd, bnd, head, c0, acc, sumw);
        edge_fma(s3, sd, bnd, head, c0, acc, sumw);
    }
    for (; p < end; p++) {
        const int s0 = __ldg(g_csr_src + p);
        edge_fma(s0, sd, bnd, head, c0, acc, sumw);
    }

    const float r = 1.f / (sumw + 1e-16f);
    const float4 b4 = __ldg((const float4*)(bias + c0));
    float4 o;
    o.x = fmaf(acc.x, r, b4.x);
    o.y = fmaf(acc.y, r, b4.y);
    o.z = fmaf(acc.z, r, b4.z);
    o.w = fmaf(acc.w, r, b4.w);
    *(float4*)(out + (size_t)n * OC + c0) = o;
}

// ---------------- launch ----------------
extern "C" void kernel_launch(void* const* d_in, const int* in_sizes, int n_in,
                              void* d_out, int out_size) {
    const float* x    = (const float*)d_in[0];
    const void*  ei   = d_in[1];
    const float* W    = (const float*)d_in[2];
    const float* att  = (const float*)d_in[3];
    const float* bias = (const float*)d_in[4];
    float*       out  = (float*)d_out;

    (void)in_sizes; (void)n_in; (void)out_size;

    k_init<<<(N_NODES + 255) / 256, 256>>>((const unsigned*)ei);
    k_gemm_mma<<<GEMM_CTAS, 256>>>(x, W, att);
    k_hist<<<(E_EDGES / 2 + 255) / 256, 256>>>(ei);
    k_scan_local<<<N_SCAN_BLOCKS, SCAN_BLK>>>();
    k_scan_bsum<<<1, 128>>>();
    k_edge2<<<(E_EDGES / 2 + 255) / 256, 256>>>(ei);
    k_aggregate<<<(N_NODES * 32 + 255) / 256, 256>>>(out, bias);
}

// round 13
// speedup vs baseline: 1.0039x; 1.0039x over previous
#include <cuda_runtime.h>
#include <cuda_fp16.h>
#include <cstdint>

#define N_NODES 100000
#define E_EDGES 1600000
#define IN_CH   128
#define HEADS   4
#define OUT_CH  32
#define OC      (HEADS * OUT_CH)   // 128
#define NEG_SLOPE 0.2f

#define SCAN_BLK 1024
#define N_SCAN_BLOCKS ((N_NODES + SCAN_BLK - 1) / SCAN_BLK)   // 98
#define GEMM_CTAS ((N_NODES + 127) / 128)                     // 782
#define ENC_NINF 0x007FFFFFu   // fenc(-inf)

// ---------------- scratch (device globals; no allocation allowed) ----------
__device__ __align__(16) __half g_hh[(size_t)GEMM_CTAS * 128 * OC]; // fp16 h (padded)
__device__ __align__(16) float  g_ssrc[N_NODES * HEADS];
__device__ __align__(16) float  g_sdst[N_NODES * HEADS];
__device__ int g_csr_src[E_EDGES];
__device__ int g_rank[E_EDGES];
__device__ int g_deg[N_NODES];            // ZERO at load; every launch restores 0
__device__ int g_off[N_NODES];            // local (per-block) exclusive prefix
__device__ int g_bsum[N_SCAN_BLOCKS];
__device__ int g_bpre[N_SCAN_BLOCKS];
__device__ unsigned g_maxss[HEADS] = {ENC_NINF, ENC_NINF, ENC_NINF, ENC_NINF};
__device__ unsigned g_maxss_ro[HEADS];    // snapshot for aggregate
__device__ int g_scan_ctr;                // ZERO at load; last block resets
__device__ int g_is64;

__device__ __forceinline__ unsigned fenc(float f) {
    unsigned u = __float_as_uint(f);
    return (u & 0x80000000u) ? ~u : (u | 0x80000000u);
}
__device__ __forceinline__ float fdec(unsigned u) {
    return (u & 0x80000000u) ? __uint_as_float(u ^ 0x80000000u)
                             : __uint_as_float(~u);
}
__device__ __forceinline__ float leaky(float v) {
    return (v >= 0.f) ? v : NEG_SLOPE * v;
}
__device__ __forceinline__ int off_of(int i) {
    return __ldg(g_off + i) + __ldg(g_bpre + (i >> 10));
}

__device__ __forceinline__ void mma16816(float& d0, float& d1, float& d2, float& d3,
                                         unsigned a0, unsigned a1, unsigned a2, unsigned a3,
                                         unsigned b0, unsigned b1) {
    asm volatile("mma.sync.aligned.m16n8k16.row.col.f32.f16.f16.f32 "
                 "{%0,%1,%2,%3}, {%4,%5,%6,%7}, {%8,%9}, {%0,%1,%2,%3};"
                 : "+f"(d0), "+f"(d1), "+f"(d2), "+f"(d3)
                 : "r"(a0), "r"(a1), "r"(a2), "r"(a3), "r"(b0), "r"(b1));
}

// ---------------- K1: tensor-core GEMM + fused scores + dtype detect -------
#define APAD 72   // 64 + 8 halves pad
__global__ void __launch_bounds__(256) k_gemm_mma(const float* __restrict__ x,
                                                  const float* __restrict__ W,
                                                  const float* __restrict__ att,
                                                  const unsigned* __restrict__ ei32) {
    __shared__ __half As[128][APAD];
    __shared__ __half Bs[128][APAD];

    const int nbase = blockIdx.x * 128;
    const int t = threadIdx.x;
    const int wid = t >> 5;
    const int lane = t & 31;
    const int g = lane >> 2;
    const int tid = lane & 3;

    // dtype detect (block 0, warp 0): int64 LE w/ small values -> odd words 0
    if (blockIdx.x == 0 && t < 32) {
        unsigned nz = ei32[2 * t + 1] | ei32[2 * (t + 32) + 1];
        const unsigned any = __ballot_sync(0xffffffffu, nz != 0u);
        if (t == 0) g_is64 = (any == 0u) ? 1 : 0;
    }

    float d[16][4];
    #pragma unroll
    for (int nt = 0; nt < 16; nt++)
        #pragma unroll
        for (int q = 0; q < 4; q++) d[nt][q] = 0.f;

    #pragma unroll
    for (int kp = 0; kp < 2; kp++) {
        #pragma unroll
        for (int i = 0; i < 8; i++) {
            const int id = t + i * 256;
            const int row = id >> 4;
            const int c4 = (id & 15) * 4;
            const int node = nbase + row;
            float4 v = make_float4(0.f, 0.f, 0.f, 0.f);
            if (node < N_NODES)
                v = __ldg((const float4*)(x + (size_t)node * IN_CH + kp * 64 + c4));
            __half h4[4] = {__float2half_rn(v.x), __float2half_rn(v.y),
                            __float2half_rn(v.z), __float2half_rn(v.w)};
            *(uint2*)&As[row][c4] = *(uint2*)h4;
        }
        #pragma unroll
        for (int i = 0; i < 8; i++) {
            const int id = t + i * 256;
            const int k = id >> 5;
            const int n4 = (id & 31) * 4;
            const float4 w4 = __ldg((const float4*)(W + (size_t)(kp * 64 + k) * OC + n4));
            Bs[n4 + 0][k] = __float2half_rn(w4.x);
            Bs[n4 + 1][k] = __float2half_rn(w4.y);
            Bs[n4 + 2][k] = __float2half_rn(w4.z);
            Bs[n4 + 3][k] = __float2half_rn(w4.w);
        }
        __syncthreads();

        const int r0 = wid * 16 + g;
        #pragma unroll
        for (int ks = 0; ks < 4; ks++) {
            const int kk = ks * 16 + tid * 2;
            const unsigned a0 = *(const unsigned*)&As[r0][kk];
            const unsigned a1 = *(const unsigned*)&As[r0 + 8][kk];
            const unsigned a2 = *(const unsigned*)&As[r0][kk + 8];
            const unsigned a3 = *(const unsigned*)&As[r0 + 8][kk + 8];
            #pragma unroll
            for (int nt = 0; nt < 16; nt++) {
                const int n = nt * 8 + g;
                const unsigned b0 = *(const unsigned*)&Bs[n][kk];
                const unsigned b1 = *(const unsigned*)&Bs[n][kk + 8];
                mma16816(d[nt][0], d[nt][1], d[nt][2], d[nt][3],
                         a0, a1, a2, a3, b0, b1);
            }
        }
        __syncthreads();
    }

    // ---- epilogue: store h (fp16) + fused scores ----
    const int node0 = nbase + wid * 16 + g;
    const int node1 = node0 + 8;

    #pragma unroll
    for (int nt = 0; nt < 16; nt++) {
        const int col = nt * 8 + tid * 2;
        const __half2 h01 = __floats2half2_rn(d[nt][0], d[nt][1]);
        const __half2 h23 = __floats2half2_rn(d[nt][2], d[nt][3]);
        *(__half2*)(g_hh + (size_t)node0 * OC + col) = h01;
        *(__half2*)(g_hh + (size_t)node1 * OC + col) = h23;
    }

    float ssA[4] = {0,0,0,0}, sdA[4] = {0,0,0,0};
    float ssB[4] = {0,0,0,0}, sdB[4] = {0,0,0,0};
    #pragma unroll
    for (int h = 0; h < 4; h++) {
        #pragma unroll
        for (int j = 0; j < 4; j++) {
            const int nt = h * 4 + j;
            const int off = j * 8 + tid * 2;
            const float2 as2 = __ldg((const float2*)(att + h * 64 + off));
            const float2 ad2 = __ldg((const float2*)(att + h * 64 + 32 + off));
            ssA[h] += d[nt][0] * as2.x + d[nt][1] * as2.y;
            sdA[h] += d[nt][0] * ad2.x + d[nt][1] * ad2.y;
            ssB[h] += d[nt][2] * as2.x + d[nt][3] * as2.y;
            sdB[h] += d[nt][2] * ad2.x + d[nt][3] * ad2.y;
        }
    }
    #pragma unroll
    for (int h = 0; h < 4; h++) {
        #pragma unroll
        for (int off = 1; off <= 2; off <<= 1) {
            ssA[h] += __shfl_xor_sync(0xffffffffu, ssA[h], off);
            sdA[h] += __shfl_xor_sync(0xffffffffu, sdA[h], off);
            ssB[h] += __shfl_xor_sync(0xffffffffu, ssB[h], off);
            sdB[h] += __shfl_xor_sync(0xffffffffu, sdB[h], off);
        }
    }
    if (tid == 0) {
        if (node0 < N_NODES) {
            *(float4*)(g_ssrc + (size_t)node0 * 4) = make_float4(ssA[0], ssA[1], ssA[2], ssA[3]);
            *(float4*)(g_sdst + (size_t)node0 * 4) = make_float4(sdA[0], sdA[1], sdA[2], sdA[3]);
        }
        if (node1 < N_NODES) {
            *(float4*)(g_ssrc + (size_t)node1 * 4) = make_float4(ssB[0], ssB[1], ssB[2], ssB[3]);
            *(float4*)(g_sdst + (size_t)node1 * 4) = make_float4(sdB[0], sdB[1], sdB[2], sdB[3]);
        }
    }
    const float NINF = -__int_as_float(0x7f800000);
    float mm[4];
    #pragma unroll
    for (int h = 0; h < 4; h++) {
        float a = (node0 < N_NODES) ? ssA[h] : NINF;
        float b = (node1 < N_NODES) ? ssB[h] : NINF;
        mm[h] = fmaxf(a, b);
        #pragma unroll
        for (int off = 4; off <= 16; off <<= 1)
            mm[h] = fmaxf(mm[h], __shfl_xor_sync(0xffffffffu, mm[h], off));
    }
    if (lane < 4)
        atomicMax(&g_maxss[lane], fenc(mm[lane]));
}

// ---------------- K2: degree histogram + rank, 2 edges/thread ---------------
__global__ void k_hist(const void* __restrict__ ei) {
    const int e = (blockIdx.x * blockDim.x + threadIdx.x) * 2;
    if (e >= E_EDGES) return;
    int d0, d1;
    if (g_is64) {
        const uint4 dv = *(const uint4*)((const long long*)ei + E_EDGES + e);
        d0 = (int)dv.x; d1 = (int)dv.z;
    } else {
        const int2 dv = *(const int2*)((const int*)ei + E_EDGES + e);
        d0 = dv.x; d1 = dv.y;
    }
    const int r0 = atomicAdd(&g_deg[d0], 1);
    const int r1 = atomicAdd(&g_deg[d1], 1);
    *(int2*)(g_rank + e) = make_int2(r0, r1);
}

// ---------------- K3: scan (local + merged last-block bsum scan) ------------
__global__ void __launch_bounds__(SCAN_BLK) k_scan() {
    __shared__ int ws[32];
    __shared__ int ws2[4];
    __shared__ int is_last;
    const int t = threadIdx.x;
    const int lane = t & 31;
    const int warp = t >> 5;
    const int i = blockIdx.x * SCAN_BLK + t;

    const int val = (i < N_NODES) ? g_deg[i] : 0;
    if (i < N_NODES) g_deg[i] = 0;           // restore invariant for next launch

    int v = val;
    #pragma unroll
    for (int d = 1; d < 32; d <<= 1) {
        const int u = __shfl_up_sync(0xffffffffu, v, d);
        if (lane >= d) v += u;
    }
    if (lane == 31) ws[warp] = v;
    __syncthreads();
    if (warp == 0) {
        int w = ws[lane];
        #pragma unroll
        for (int d = 1; d < 32; d <<= 1) {
            const int u = __shfl_up_sync(0xffffffffu, w, d);
            if (lane >= d) w += u;
        }
        ws[lane] = w;
    }
    __syncthreads();
    const int incl = v + (warp ? ws[warp - 1] : 0);
    if (i < N_NODES) g_off[i] = incl - val;

    if (t == SCAN_BLK - 1) {
        g_bsum[blockIdx.x] = incl;
        __threadfence();
        is_last = (atomicAdd(&g_scan_ctr, 1) == (int)gridDim.x - 1);
    }
    __syncthreads();

    if (is_last) {                           // block-uniform
        // scan the 98 block totals (threads 0..127)
        int v2 = 0, val2 = 0;
        if (t < 128) {
            val2 = (t < N_SCAN_BLOCKS) ? g_bsum[t] : 0;
            v2 = val2;
            #pragma unroll
            for (int d = 1; d < 32; d <<= 1) {
                const int u = __shfl_up_sync(0xffffffffu, v2, d);
                if (lane >= d) v2 += u;
            }
            if (lane == 31) ws2[warp] = v2;
        }
        __syncthreads();
        if (t < 128) {
            int wpre = 0;
            #pragma unroll
            for (int w = 0; w < 4; w++) if (w < warp) wpre += ws2[w];
            if (t < N_SCAN_BLOCKS) g_bpre[t] = v2 - val2 + wpre;
        }
        // snapshot + reset maxss; reset counter
        if (t < HEADS) {
            g_maxss_ro[t] = g_maxss[t];
            g_maxss[t] = ENC_NINF;
        }
        if (t == 0) g_scan_ctr = 0;
    }
}

// ---------------- K4: CSR scatter, 2 edges/thread, no atomics ---------------
__global__ void k_edge2(const void* __restrict__ ei) {
    const int e = (blockIdx.x * blockDim.x + threadIdx.x) * 2;
    if (e >= E_EDGES) return;
    int s0, s1, d0, d1;
    if (g_is64) {
        const uint4 sv = *(const uint4*)((const long long*)ei + e);
        const uint4 dv = *(const uint4*)((const long long*)ei + E_EDGES + e);
        s0 = (int)sv.x; s1 = (int)sv.z;
        d0 = (int)dv.x; d1 = (int)dv.z;
    } else {
        const int2 sv = *(const int2*)((const int*)ei + e);
        const int2 dv = *(const int2*)((const int*)ei + E_EDGES + e);
        s0 = sv.x; s1 = sv.y;
        d0 = dv.x; d1 = dv.y;
    }
    const int2 rk = *(const int2*)(g_rank + e);
    g_csr_src[off_of(d0) + rk.x] = s0;
    g_csr_src[off_of(d1) + rk.y] = s1;
}

// ---------------- K5: aggregation w/ on-the-fly softmax (1 warp/node) ------
__device__ __forceinline__ void edge_fma(int src, float sd, float bnd, int head, int c0,
                                         float4& acc, float& sumw) {
    const float ss = __ldg(g_ssrc + (size_t)src * 4 + head);
    const float w = __expf(leaky(ss + sd) - bnd);
    const uint2 r = *(const uint2*)(g_hh + (size_t)src * OC + c0);
    const float2 a = __half22float2(*(const __half2*)&r.x);
    const float2 b = __half22float2(*(const __half2*)&r.y);
    acc.x = fmaf(w, a.x, acc.x); acc.y = fmaf(w, a.y, acc.y);
    acc.z = fmaf(w, b.x, acc.z); acc.w = fmaf(w, b.y, acc.w);
    sumw += w;
}

__global__ void __launch_bounds__(256) k_aggregate(float* __restrict__ out,
                                                   const float* __restrict__ bias) {
    const int n = (blockIdx.x * blockDim.x + threadIdx.x) >> 5;
    if (n >= N_NODES) return;
    const int lane = threadIdx.x & 31;
    const int head = lane >> 3;
    const int c0 = lane * 4;

    const int beg = off_of(n);
    const int end = (n + 1 < N_NODES) ? off_of(n + 1) : E_EDGES;

    const float sd = __ldg(g_sdst + (size_t)n * 4 + head);
    const float bnd = leaky(fdec(g_maxss_ro[head]) + sd);

    float4 acc = make_float4(0.f, 0.f, 0.f, 0.f);
    float sumw = 0.f;

    int p = beg;
    for (; p + 4 <= end; p += 4) {
        const int s0 = __ldg(g_csr_src + p);
        const int s1 = __ldg(g_csr_src + p + 1);
        const int s2 = __ldg(g_csr_src + p + 2);
        const int s3 = __ldg(g_csr_src + p + 3);
        edge_fma(s0, sd, bnd, head, c0, acc, sumw);
        edge_fma(s1, sd, bnd, head, c0, acc, sumw);
        edge_fma(s2, sd, bnd, head, c0, acc, sumw);
        edge_fma(s3, sd, bnd, head, c0, acc, sumw);
    }
    for (; p < end; p++) {
        const int s0 = __ldg(g_csr_src + p);
        edge_fma(s0, sd, bnd, head, c0, acc, sumw);
    }

    const float r = 1.f / (sumw + 1e-16f);
    const float4 b4 = __ldg((const float4*)(bias + c0));
    float4 o;
    o.x = fmaf(acc.x, r, b4.x);
    o.y = fmaf(acc.y, r, b4.y);
    o.z = fmaf(acc.z, r, b4.z);
    o.w = fmaf(acc.w, r, b4.w);
    *(float4*)(out + (size_t)n * OC + c0) = o;
}

// ---------------- launch ----------------
extern "C" void kernel_launch(void* const* d_in, const int* in_sizes, int n_in,
                              void* d_out, int out_size) {
    const float* x    = (const float*)d_in[0];
    const void*  ei   = d_in[1];
    const float* W    = (const float*)d_in[2];
    const float* att  = (const float*)d_in[3];
    const float* bias = (const float*)d_in[4];
    float*       out  = (float*)d_out;

    (void)in_sizes; (void)n_in; (void)out_size;

    k_gemm_mma<<<GEMM_CTAS, 256>>>(x, W, att, (const unsigned*)ei);
    k_hist<<<(E_EDGES / 2 + 255) / 256, 256>>>(ei);
    k_scan<<<N_SCAN_BLOCKS, SCAN_BLK>>>();
    k_edge2<<<(E_EDGES / 2 + 255) / 256, 256>>>(ei);
    k_aggregate<<<(N_NODES * 32 + 255) / 256, 256>>>(out, bias);
}

// round 14
// speedup vs baseline: 1.0263x; 1.0224x over previous
#include <cuda_runtime.h>
#include <cuda_fp16.h>
#include <cstdint>

#define N_NODES 100000
#define E_EDGES 1600000
#define IN_CH   128
#define HEADS   4
#define OUT_CH  32
#define OC      (HEADS * OUT_CH)   // 128
#define NEG_SLOPE 0.2f

#define SCAN_BLK 1024
#define N_SCAN_BLOCKS ((N_NODES + SCAN_BLK - 1) / SCAN_BLK)   // 98
#define GEMM_CTAS ((N_NODES + 127) / 128)                     // 782
#define ENC_NINF 0x007FFFFFu   // fenc(-inf)

// ---------------- scratch (device globals; no allocation allowed) ----------
__device__ __align__(16) __half g_hh[(size_t)GEMM_CTAS * 128 * OC]; // fp16 h (padded)
__device__ __align__(16) float  g_ssrc[N_NODES * HEADS];
__device__ __align__(16) float  g_sdst[N_NODES * HEADS];
__device__ int g_csr_src[E_EDGES];
__device__ int g_rank[E_EDGES];
__device__ int g_deg[N_NODES];            // ZERO at load; every launch restores 0
__device__ int g_off[N_NODES];            // local (per-block) exclusive prefix
__device__ int g_bsum[N_SCAN_BLOCKS];
__device__ int g_bpre[N_SCAN_BLOCKS];
__device__ unsigned g_maxss[HEADS] = {ENC_NINF, ENC_NINF, ENC_NINF, ENC_NINF};
__device__ unsigned g_maxss_ro[HEADS];    // snapshot for aggregate
__device__ int g_scan_ctr;                // ZERO at load; last block resets
__device__ int g_is64;

__device__ __forceinline__ unsigned fenc(float f) {
    unsigned u = __float_as_uint(f);
    return (u & 0x80000000u) ? ~u : (u | 0x80000000u);
}
__device__ __forceinline__ float fdec(unsigned u) {
    return (u & 0x80000000u) ? __uint_as_float(u ^ 0x80000000u)
                             : __uint_as_float(~u);
}
__device__ __forceinline__ float leaky(float v) {
    return (v >= 0.f) ? v : NEG_SLOPE * v;
}
__device__ __forceinline__ int off_of(int i) {
    return __ldg(g_off + i) + __ldg(g_bpre + (i >> 10));
}

__device__ __forceinline__ void mma16816(float& d0, float& d1, float& d2, float& d3,
                                         unsigned a0, unsigned a1, unsigned a2, unsigned a3,
                                         unsigned b0, unsigned b1) {
    asm volatile("mma.sync.aligned.m16n8k16.row.col.f32.f16.f16.f32 "
                 "{%0,%1,%2,%3}, {%4,%5,%6,%7}, {%8,%9}, {%0,%1,%2,%3};"
                 : "+f"(d0), "+f"(d1), "+f"(d2), "+f"(d3)
                 : "r"(a0), "r"(a1), "r"(a2), "r"(a3), "r"(b0), "r"(b1));
}

// ---------------- K1: tensor-core GEMM + fused scores + dtype detect -------
#define APAD 72   // 64 + 8 halves pad
__global__ void __launch_bounds__(256) k_gemm_mma(const float* __restrict__ x,
                                                  const float* __restrict__ W,
                                                  const float* __restrict__ att,
                                                  const unsigned* __restrict__ ei32) {
    __shared__ __half As[128][APAD];
    __shared__ __half Bs[128][APAD];

    const int nbase = blockIdx.x * 128;
    const int t = threadIdx.x;
    const int wid = t >> 5;
    const int lane = t & 31;
    const int g = lane >> 2;
    const int tid = lane & 3;

    // dtype detect (block 0, warp 0): int64 LE w/ small values -> odd words 0
    if (blockIdx.x == 0 && t < 32) {
        unsigned nz = ei32[2 * t + 1] | ei32[2 * (t + 32) + 1];
        const unsigned any = __ballot_sync(0xffffffffu, nz != 0u);
        if (t == 0) g_is64 = (any == 0u) ? 1 : 0;
    }

    float d[16][4];
    #pragma unroll
    for (int nt = 0; nt < 16; nt++)
        #pragma unroll
        for (int q = 0; q < 4; q++) d[nt][q] = 0.f;

    #pragma unroll
    for (int kp = 0; kp < 2; kp++) {
        #pragma unroll
        for (int i = 0; i < 8; i++) {
            const int id = t + i * 256;
            const int row = id >> 4;
            const int c4 = (id & 15) * 4;
            const int node = nbase + row;
            float4 v = make_float4(0.f, 0.f, 0.f, 0.f);
            if (node < N_NODES)
                v = __ldg((const float4*)(x + (size_t)node * IN_CH + kp * 64 + c4));
            __half h4[4] = {__float2half_rn(v.x), __float2half_rn(v.y),
                            __float2half_rn(v.z), __float2half_rn(v.w)};
            *(uint2*)&As[row][c4] = *(uint2*)h4;
        }
        #pragma unroll
        for (int i = 0; i < 8; i++) {
            const int id = t + i * 256;
            const int k = id >> 5;
            const int n4 = (id & 31) * 4;
            const float4 w4 = __ldg((const float4*)(W + (size_t)(kp * 64 + k) * OC + n4));
            Bs[n4 + 0][k] = __float2half_rn(w4.x);
            Bs[n4 + 1][k] = __float2half_rn(w4.y);
            Bs[n4 + 2][k] = __float2half_rn(w4.z);
            Bs[n4 + 3][k] = __float2half_rn(w4.w);
        }
        __syncthreads();

        const int r0 = wid * 16 + g;
        #pragma unroll
        for (int ks = 0; ks < 4; ks++) {
            const int kk = ks * 16 + tid * 2;
            const unsigned a0 = *(const unsigned*)&As[r0][kk];
            const unsigned a1 = *(const unsigned*)&As[r0 + 8][kk];
            const unsigned a2 = *(const unsigned*)&As[r0][kk + 8];
            const unsigned a3 = *(const unsigned*)&As[r0 + 8][kk + 8];
            #pragma unroll
            for (int nt = 0; nt < 16; nt++) {
                const int n = nt * 8 + g;
                const unsigned b0 = *(const unsigned*)&Bs[n][kk];
                const unsigned b1 = *(const unsigned*)&Bs[n][kk + 8];
                mma16816(d[nt][0], d[nt][1], d[nt][2], d[nt][3],
                         a0, a1, a2, a3, b0, b1);
            }
        }
        __syncthreads();
    }

    // ---- epilogue: store h (fp16) + fused scores ----
    const int node0 = nbase + wid * 16 + g;
    const int node1 = node0 + 8;

    #pragma unroll
    for (int nt = 0; nt < 16; nt++) {
        const int col = nt * 8 + tid * 2;
        const __half2 h01 = __floats2half2_rn(d[nt][0], d[nt][1]);
        const __half2 h23 = __floats2half2_rn(d[nt][2], d[nt][3]);
        *(__half2*)(g_hh + (size_t)node0 * OC + col) = h01;
        *(__half2*)(g_hh + (size_t)node1 * OC + col) = h23;
    }

    float ssA[4] = {0,0,0,0}, sdA[4] = {0,0,0,0};
    float ssB[4] = {0,0,0,0}, sdB[4] = {0,0,0,0};
    #pragma unroll
    for (int h = 0; h < 4; h++) {
        #pragma unroll
        for (int j = 0; j < 4; j++) {
            const int nt = h * 4 + j;
            const int off = j * 8 + tid * 2;
            const float2 as2 = __ldg((const float2*)(att + h * 64 + off));
            const float2 ad2 = __ldg((const float2*)(att + h * 64 + 32 + off));
            ssA[h] += d[nt][0] * as2.x + d[nt][1] * as2.y;
            sdA[h] += d[nt][0] * ad2.x + d[nt][1] * ad2.y;
            ssB[h] += d[nt][2] * as2.x + d[nt][3] * as2.y;
            sdB[h] += d[nt][2] * ad2.x + d[nt][3] * ad2.y;
        }
    }
    #pragma unroll
    for (int h = 0; h < 4; h++) {
        #pragma unroll
        for (int off = 1; off <= 2; off <<= 1) {
            ssA[h] += __shfl_xor_sync(0xffffffffu, ssA[h], off);
            sdA[h] += __shfl_xor_sync(0xffffffffu, sdA[h], off);
            ssB[h] += __shfl_xor_sync(0xffffffffu, ssB[h], off);
            sdB[h] += __shfl_xor_sync(0xffffffffu, sdB[h], off);
        }
    }
    if (tid == 0) {
        if (node0 < N_NODES) {
            *(float4*)(g_ssrc + (size_t)node0 * 4) = make_float4(ssA[0], ssA[1], ssA[2], ssA[3]);
            *(float4*)(g_sdst + (size_t)node0 * 4) = make_float4(sdA[0], sdA[1], sdA[2], sdA[3]);
        }
        if (node1 < N_NODES) {
            *(float4*)(g_ssrc + (size_t)node1 * 4) = make_float4(ssB[0], ssB[1], ssB[2], ssB[3]);
            *(float4*)(g_sdst + (size_t)node1 * 4) = make_float4(sdB[0], sdB[1], sdB[2], sdB[3]);
        }
    }
    const float NINF = -__int_as_float(0x7f800000);
    float mm[4];
    #pragma unroll
    for (int h = 0; h < 4; h++) {
        float a = (node0 < N_NODES) ? ssA[h] : NINF;
        float b = (node1 < N_NODES) ? ssB[h] : NINF;
        mm[h] = fmaxf(a, b);
        #pragma unroll
        for (int off = 4; off <= 16; off <<= 1)
            mm[h] = fmaxf(mm[h], __shfl_xor_sync(0xffffffffu, mm[h], off));
    }
    if (lane < 4)
        atomicMax(&g_maxss[lane], fenc(mm[lane]));
}

// ---------------- K2: degree histogram + rank, 2 edges/thread ---------------
__global__ void k_hist(const void* __restrict__ ei) {
    const int e = (blockIdx.x * blockDim.x + threadIdx.x) * 2;
    if (e >= E_EDGES) return;
    int d0, d1;
    if (g_is64) {
        const uint4 dv = *(const uint4*)((const long long*)ei + E_EDGES + e);
        d0 = (int)dv.x; d1 = (int)dv.z;
    } else {
        const int2 dv = *(const int2*)((const int*)ei + E_EDGES + e);
        d0 = dv.x; d1 = dv.y;
    }
    const int r0 = atomicAdd(&g_deg[d0], 1);
    const int r1 = atomicAdd(&g_deg[d1], 1);
    *(int2*)(g_rank + e) = make_int2(r0, r1);
}

// ---------------- K3: scan (local + merged last-block bsum scan) ------------
__global__ void __launch_bounds__(SCAN_BLK) k_scan() {
    __shared__ int ws[32];
    __shared__ int ws2[4];
    __shared__ int is_last;
    const int t = threadIdx.x;
    const int lane = t & 31;
    const int warp = t >> 5;
    const int i = blockIdx.x * SCAN_BLK + t;

    const int val = (i < N_NODES) ? g_deg[i] : 0;
    if (i < N_NODES) g_deg[i] = 0;           // restore invariant for next launch

    int v = val;
    #pragma unroll
    for (int d = 1; d < 32; d <<= 1) {
        const int u = __shfl_up_sync(0xffffffffu, v, d);
        if (lane >= d) v += u;
    }
    if (lane == 31) ws[warp] = v;
    __syncthreads();
    if (warp == 0) {
        int w = ws[lane];
        #pragma unroll
        for (int d = 1; d < 32; d <<= 1) {
            const int u = __shfl_up_sync(0xffffffffu, w, d);
            if (lane >= d) w += u;
        }
        ws[lane] = w;
    }
    __syncthreads();
    const int incl = v + (warp ? ws[warp - 1] : 0);
    if (i < N_NODES) g_off[i] = incl - val;

    if (t == SCAN_BLK - 1) {
        g_bsum[blockIdx.x] = incl;
        __threadfence();
        is_last = (atomicAdd(&g_scan_ctr, 1) == (int)gridDim.x - 1);
    }
    __syncthreads();

    if (is_last) {                           // block-uniform
        int v2 = 0, val2 = 0;
        if (t < 128) {
            val2 = (t < N_SCAN_BLOCKS) ? g_bsum[t] : 0;
            v2 = val2;
            #pragma unroll
            for (int d = 1; d < 32; d <<= 1) {
                const int u = __shfl_up_sync(0xffffffffu, v2, d);
                if (lane >= d) v2 += u;
            }
            if (lane == 31) ws2[warp] = v2;
        }
        __syncthreads();
        if (t < 128) {
            int wpre = 0;
            #pragma unroll
            for (int w = 0; w < 4; w++) if (w < warp) wpre += ws2[w];
            if (t < N_SCAN_BLOCKS) g_bpre[t] = v2 - val2 + wpre;
        }
        if (t < HEADS) {
            g_maxss_ro[t] = g_maxss[t];
            g_maxss[t] = ENC_NINF;
        }
        if (t == 0) g_scan_ctr = 0;
    }
}

// ---------------- K4: CSR scatter, 2 edges/thread, no atomics ---------------
__global__ void k_edge2(const void* __restrict__ ei) {
    const int e = (blockIdx.x * blockDim.x + threadIdx.x) * 2;
    if (e >= E_EDGES) return;
    int s0, s1, d0, d1;
    if (g_is64) {
        const uint4 sv = *(const uint4*)((const long long*)ei + e);
        const uint4 dv = *(const uint4*)((const long long*)ei + E_EDGES + e);
        s0 = (int)sv.x; s1 = (int)sv.z;
        d0 = (int)dv.x; d1 = (int)dv.z;
    } else {
        const int2 sv = *(const int2*)((const int*)ei + e);
        const int2 dv = *(const int2*)((const int*)ei + E_EDGES + e);
        s0 = sv.x; s1 = sv.y;
        d0 = dv.x; d1 = dv.y;
    }
    const int2 rk = *(const int2*)(g_rank + e);
    g_csr_src[off_of(d0) + rk.x] = s0;
    g_csr_src[off_of(d1) + rk.y] = s1;
}

// ---------------- K5: aggregation, 2 edges per warp-iteration ---------------
// Warp = node n. Lane = slot*16 + cl; slot handles edge p+slot, cl covers
// channels [cl*8, cl*8+8) (one uint4 of fp16). head = cl>>2.
__global__ void __launch_bounds__(256) k_aggregate(float* __restrict__ out,
                                                   const float* __restrict__ bias) {
    const int n = (blockIdx.x * blockDim.x + threadIdx.x) >> 5;
    if (n >= N_NODES) return;
    const int lane = threadIdx.x & 31;
    const int half = lane >> 4;         // edge slot 0/1
    const int cl = lane & 15;           // channel-octet index
    const int head = cl >> 2;

    const int beg = off_of(n);
    const int end = (n + 1 < N_NODES) ? off_of(n + 1) : E_EDGES;

    const float sd = __ldg(g_sdst + (size_t)n * 4 + head);
    const float bnd = leaky(fdec(g_maxss_ro[head]) + sd);

    float acc[8] = {0.f, 0.f, 0.f, 0.f, 0.f, 0.f, 0.f, 0.f};
    float sumw = 0.f;

    #pragma unroll 4
    for (int p = beg + half; p < end; p += 2) {
        const int src = __ldg(g_csr_src + p);
        const float ss = __ldg(g_ssrc + (size_t)src * 4 + head);
        const float w = __expf(leaky(ss + sd) - bnd);
        const uint4 r = *(const uint4*)(g_hh + (size_t)src * OC + cl * 8);
        const float2 f0 = __half22float2(*(const __half2*)&r.x);
        const float2 f1 = __half22float2(*(const __half2*)&r.y);
        const float2 f2 = __half22float2(*(const __half2*)&r.z);
        const float2 f3 = __half22float2(*(const __half2*)&r.w);
        acc[0] = fmaf(w, f0.x, acc[0]); acc[1] = fmaf(w, f0.y, acc[1]);
        acc[2] = fmaf(w, f1.x, acc[2]); acc[3] = fmaf(w, f1.y, acc[3]);
        acc[4] = fmaf(w, f2.x, acc[4]); acc[5] = fmaf(w, f2.y, acc[5]);
        acc[6] = fmaf(w, f3.x, acc[6]); acc[7] = fmaf(w, f3.y, acc[7]);
        if ((cl & 3) == 0) sumw += w;   // one lane per (slot, head) counts
    }

    // combine the two edge slots
    #pragma unroll
    for (int i = 0; i < 8; i++)
        acc[i] += __shfl_xor_sync(0xffffffffu, acc[i], 16);
    sumw += __shfl_xor_sync(0xffffffffu, sumw, 16);
    sumw = __shfl_sync(0xffffffffu, sumw, lane & 28);  // broadcast within head quad

    const float r = 1.f / (sumw + 1e-16f);
    if (half == 0) {
        const int c0 = cl * 8;
        const float4 b0 = __ldg((const float4*)(bias + c0));
        const float4 b1 = __ldg((const float4*)(bias + c0 + 4));
        float4 o0, o1;
        o0.x = fmaf(acc[0], r, b0.x); o0.y = fmaf(acc[1], r, b0.y);
        o0.z = fmaf(acc[2], r, b0.z); o0.w = fmaf(acc[3], r, b0.w);
        o1.x = fmaf(acc[4], r, b1.x); o1.y = fmaf(acc[5], r, b1.y);
        o1.z = fmaf(acc[6], r, b1.z); o1.w = fmaf(acc[7], r, b1.w);
        *(float4*)(out + (size_t)n * OC + c0) = o0;
        *(float4*)(out + (size_t)n * OC + c0 + 4) = o1;
    }
}

// ---------------- launch ----------------
extern "C" void kernel_launch(void* const* d_in, const int* in_sizes, int n_in,
                              void* d_out, int out_size) {
    const float* x    = (const float*)d_in[0];
    const void*  ei   = d_in[1];
    const float* W    = (const float*)d_in[2];
    const float* att  = (const float*)d_in[3];
    const float* bias = (const float*)d_in[4];
    float*       out  = (float*)d_out;

    (void)in_sizes; (void)n_in; (void)out_size;

    k_gemm_mma<<<GEMM_CTAS, 256>>>(x, W, att, (const unsigned*)ei);
    k_hist<<<(E_EDGES / 2 + 255) / 256, 256>>>(ei);
    k_scan<<<N_SCAN_BLOCKS, SCAN_BLK>>>();
    k_edge2<<<(E_EDGES / 2 + 255) / 256, 256>>>(ei);
    k_aggregate<<<(N_NODES * 32 + 255) / 256, 256>>>(out, bias);
}